// round 12
// baseline (speedup 1.0000x reference)
#include <cuda_runtime.h>
#include <cuda_fp16.h>
#include <cstdint>

#define EPS_F 1e-15f

static const int N_GCN  = 8192;
static const int DIN_   = 256;
static const int DOUT_  = 256;

// ---------------------------------------------------------------------------
// Scratch (__device__ globals; no cudaMalloc allowed)
// ---------------------------------------------------------------------------
__device__ float g_d[8192];
__device__ __align__(16) float  g_g[8192 * 256];            // g = d*(x@W^T) fp32, [m][n]
__device__ __align__(16) __half g_gT_h[256 * 8192];         // gT hi fp16, [n][k]
__device__ __align__(16) __half g_gT_l[256 * 8192];         // gT lo fp16, [n][k]

// ---------------------------------------------------------------------------
// PTX helpers (plain sm_103-legal: ldmatrix / mma.sync / cp.async)
// ---------------------------------------------------------------------------
__device__ __forceinline__ uint32_t smem_to_u32(const void* p) {
    uint32_t a;
    asm("{ .reg .u64 t; cvta.to.shared.u64 t, %1; cvt.u32.u64 %0, t; }" : "=r"(a) : "l"(p));
    return a;
}

#define LDMX4(R, addr) \
    asm volatile("ldmatrix.sync.aligned.m8n8.x4.shared.b16 {%0,%1,%2,%3}, [%4];" \
        : "=r"((R)[0]), "=r"((R)[1]), "=r"((R)[2]), "=r"((R)[3]) : "r"(addr))

#define MMA16816(d, a, b0, b1) \
    asm volatile("mma.sync.aligned.m16n8k16.row.col.f32.f16.f16.f32 " \
        "{%0,%1,%2,%3}, {%4,%5,%6,%7}, {%8,%9}, {%0,%1,%2,%3};" \
        : "+f"((d)[0]), "+f"((d)[1]), "+f"((d)[2]), "+f"((d)[3]) \
        : "r"((a)[0]), "r"((a)[1]), "r"((a)[2]), "r"((a)[3]), "r"(b0), "r"(b1))

#define CP_ASYNC16(dst, src) \
    asm volatile("cp.async.cg.shared.global [%0], [%1], 16;" :: "r"(dst), "l"(src) : "memory")
#define CP_COMMIT() asm volatile("cp.async.commit_group;" ::: "memory")
#define CP_WAIT0()  asm volatile("cp.async.wait_group 0;" ::: "memory")

__device__ __forceinline__ uint32_t h2u(__half2 v) { return *reinterpret_cast<uint32_t*>(&v); }

// ---------------------------------------------------------------------------
// Kernel A: read-only degree computation (proven: 80% HBM)
// ---------------------------------------------------------------------------
__global__ void deg_kernel(const float* __restrict__ A, int N) {
    int row = blockIdx.x;
    const float4* Ar = (const float4*)(A + (size_t)row * N);
    int n4 = N >> 2;
    float s = 0.0f;
    for (int j = threadIdx.x; j < n4; j += blockDim.x) {
        float4 v = Ar[j];
        s += (v.x > EPS_F ? 1.0f : 0.0f);
        s += (v.y > EPS_F ? 1.0f : 0.0f);
        s += (v.z > EPS_F ? 1.0f : 0.0f);
        s += (v.w > EPS_F ? 1.0f : 0.0f);
    }
    __shared__ float red[256];
    red[threadIdx.x] = s;
    __syncthreads();
    for (int off = 128; off > 0; off >>= 1) {
        if (threadIdx.x < off) red[threadIdx.x] += red[threadIdx.x + off];
        __syncthreads();
    }
    if (threadIdx.x == 0) g_d[row] = rsqrtf(1.0f + red[0]);
}

// ---------------------------------------------------------------------------
// Kernel B: g = d*(x@W^T) fp32 + transposed fp16 hi/lo splits (proven)
// ---------------------------------------------------------------------------
__global__ void xw_kernel(const float* __restrict__ x,
                          const float* __restrict__ W) {
    __shared__ float xs[16][68];
    __shared__ float ws[16][68];

    int bm = blockIdx.x * 64;
    int bn = blockIdx.y * 64;
    int tid = threadIdx.x;
    int tx = tid & 15;
    int ty = tid >> 4;

    float acc[4][4];
#pragma unroll
    for (int i = 0; i < 4; i++)
#pragma unroll
        for (int j = 0; j < 4; j++) acc[i][j] = 0.0f;

    for (int kt = 0; kt < DIN_; kt += 16) {
        {
            int r = tid >> 2, c = tid & 3;
            float4 v = *(const float4*)(x + (size_t)(bm + r) * DIN_ + kt + c * 4);
            xs[c * 4 + 0][r] = v.x; xs[c * 4 + 1][r] = v.y;
            xs[c * 4 + 2][r] = v.z; xs[c * 4 + 3][r] = v.w;
        }
        {
            int r = tid >> 2, c = tid & 3;
            float4 v = *(const float4*)(W + (size_t)(bn + r) * DIN_ + kt + c * 4);
            ws[c * 4 + 0][r] = v.x; ws[c * 4 + 1][r] = v.y;
            ws[c * 4 + 2][r] = v.z; ws[c * 4 + 3][r] = v.w;
        }
        __syncthreads();
#pragma unroll
        for (int k = 0; k < 16; k++) {
            float4 a = *(const float4*)&xs[k][ty * 4];
            float4 b = *(const float4*)&ws[k][tx * 4];
            float av[4] = {a.x, a.y, a.z, a.w};
            float bv[4] = {b.x, b.y, b.z, b.w};
#pragma unroll
            for (int i = 0; i < 4; i++)
#pragma unroll
                for (int j = 0; j < 4; j++) acc[i][j] += av[i] * bv[j];
        }
        __syncthreads();
    }

    int m0 = bm + ty * 4;
    float dm[4];
#pragma unroll
    for (int i = 0; i < 4; i++) dm[i] = g_d[m0 + i];

#pragma unroll
    for (int j = 0; j < 4; j++) {
        int n = bn + tx * 4 + j;
        float gv[4];
#pragma unroll
        for (int i = 0; i < 4; i++) {
            gv[i] = dm[i] * acc[i][j];
            g_g[(size_t)(m0 + i) * DOUT_ + n] = gv[i];
        }
        __half2 h01 = __floats2half2_rn(gv[0], gv[1]);
        __half2 h23 = __floats2half2_rn(gv[2], gv[3]);
        float2 f01 = __half22float2(h01);
        float2 f23 = __half22float2(h23);
        __half2 l01 = __floats2half2_rn(gv[0] - f01.x, gv[1] - f01.y);
        __half2 l23 = __floats2half2_rn(gv[2] - f23.x, gv[3] - f23.y);
        *(uint2*)(&g_gT_h[(size_t)n * N_GCN + m0]) = make_uint2(h2u(h01), h2u(h23));
        *(uint2*)(&g_gT_l[(size_t)n * N_GCN + m0]) = make_uint2(h2u(l01), h2u(l23));
    }
}

// ---------------------------------------------------------------------------
// Kernel C: warp-MMA GEMM. out = relu(d * (A@g + g)) + fused A passthrough copy.
// CTA 128x128, BK=64, 16 warps (4M x 4N), warp tile 32x32.
// BK=64 @ 16 warps: chunk count 128 (sync overhead halved vs R10); A staging
// only v[4]/thread so no register pressure (R7's BK=64 failure was 8-warp regs).
// fp16 2-term split: Ah*gh + Ah*gl (rel_err ~1.8e-4).
// Dynamic SMEM 108KB double buffered; stride 144B, conflict-free LDSM.
// ---------------------------------------------------------------------------
static const int BM = 128, BN = 128, BK = 64;
static const int TSTRIDE = 144;                // 64 fp16 = 128B + 16B pad
static const int TILE_B  = 128 * TSTRIDE;      // 18432 B
static const int BUF_B   = 3 * TILE_B;         // Ah, Bh, Bl = 55296 B
static const int SMEM_TOTAL_C = 2 * BUF_B;     // 110592 B (dynamic)

__global__ void __launch_bounds__(512, 1)
agemm_mma(const float* __restrict__ A, float* __restrict__ out,
          float* __restrict__ Acopy, int doCopy, int K) {
    extern __shared__ char smem[];
    uint32_t sbase = smem_to_u32(smem);

    int tid  = threadIdx.x;
    int lane = tid & 31;
    int wid  = tid >> 5;
    int wm = wid & 3;                  // 0..3 -> 32-row block
    int wn = wid >> 2;                 // 0..3 -> 32-col block
    int bm = blockIdx.x * BM;
    int by = blockIdx.y;
    int bn = by * BN;

    // A loader: each thread owns 16 of 64 k of one row of the 128x64 tile
    int arow = tid >> 2;               // 0..127
    int aq   = tid & 3;                // 16 fp32 elems each
    const float* Aptr = A + (size_t)(bm + arow) * K + aq * 16;
    float* Cptr = Acopy ? (Acopy + (size_t)(bm + arow) * K + aq * 16) : (float*)0;
    uint32_t a_soff = (uint32_t)arow * TSTRIDE + aq * 32;

    uint32_t aoff0 = (uint32_t)(wm * 32 + (lane & 15)) * TSTRIDE + (lane >> 4) * 16;
    uint32_t brow  = (lane & 7) + ((lane >> 4) & 1) * 8;
    uint32_t boff0 = (uint32_t)(wn * 32 + brow) * TSTRIDE + ((lane >> 3) & 1) * 16;

    float acc[2][4][4];
#pragma unroll
    for (int f = 0; f < 2; f++)
#pragma unroll
        for (int n = 0; n < 4; n++)
#pragma unroll
            for (int e = 0; e < 4; e++) acc[f][n][e] = 0.0f;

    const int NC = K / BK;    // 128

    auto issue_B = [&](int buf, int kt) {
#pragma unroll
        for (int j = 0; j < 4; j++) {
            int id = j * 512 + tid;            // 0..2047
            int split = id >> 10;              // 0=hi, 1=lo
            int rem = id & 1023;
            int n = rem >> 3, seg = rem & 7;   // 8 x 16B segments = 64 fp16
            const __half* src = (split ? g_gT_l : g_gT_h) + (size_t)(bn + n) * K + kt + seg * 8;
            uint32_t dst = sbase + buf * BUF_B + (1 + split) * TILE_B + n * TSTRIDE + seg * 16;
            CP_ASYNC16(dst, src);
        }
    };

    // store A hi tile (16 fp16 = two uint4) to smem; copy raw fp32 chunk
    auto store_A = [&](int buf, const float4* v, int chunk) {
        char* base = smem + buf * BUF_B;
#pragma unroll
        for (int q = 0; q < 2; q++) {
            __half2 ha = __floats2half2_rn(v[2 * q].x, v[2 * q].y);
            __half2 hb = __floats2half2_rn(v[2 * q].z, v[2 * q].w);
            __half2 hc = __floats2half2_rn(v[2 * q + 1].x, v[2 * q + 1].y);
            __half2 hd = __floats2half2_rn(v[2 * q + 1].z, v[2 * q + 1].w);
            *(uint4*)(base + a_soff + q * 16) = make_uint4(h2u(ha), h2u(hb), h2u(hc), h2u(hd));
        }
        if (doCopy && (chunk >> 6) == by) {
            float* cp = Cptr + (size_t)chunk * BK;
#pragma unroll
            for (int q = 0; q < 4; q++) *(float4*)(cp + q * 4) = v[q];
        }
    };

    // ---- prologue: chunk 0 -> buf 0 ----
    {
        float4 v[4];
#pragma unroll
        for (int q = 0; q < 4; q++) v[q] = *(const float4*)(Aptr + q * 4);
        issue_B(0, 0);
        CP_COMMIT();
        store_A(0, v, 0);
    }

    for (int i = 0; i < NC; i++) {
        int cur = i & 1, nxt = cur ^ 1;
        CP_WAIT0();
        __syncthreads();

        float4 v[4];
        bool more = (i + 1) < NC;
        if (more) {
            const float* Ap = Aptr + (size_t)(i + 1) * BK;
#pragma unroll
            for (int q = 0; q < 4; q++) v[q] = *(const float4*)(Ap + q * 4);
            issue_B(nxt, (i + 1) * BK);
            CP_COMMIT();
        }

        uint32_t sa_h = sbase + cur * BUF_B;
        uint32_t sb_h = sa_h + TILE_B;
        uint32_t sb_l = sa_h + 2 * TILE_B;

#pragma unroll
        for (int kh = 0; kh < 4; kh++) {
            uint32_t ah[2][4], bh[2][4], bl[2][4];
            uint32_t ka = aoff0 + kh * 32;
            uint32_t kb = boff0 + kh * 32;
#pragma unroll
            for (int f = 0; f < 2; f++) LDMX4(ah[f], sa_h + ka + f * (16 * TSTRIDE));
#pragma unroll
            for (int p = 0; p < 2; p++) LDMX4(bh[p], sb_h + kb + p * (16 * TSTRIDE));
#pragma unroll
            for (int p = 0; p < 2; p++) LDMX4(bl[p], sb_l + kb + p * (16 * TSTRIDE));

            // term-major: same-acc reuse distance = 8 MMAs
#pragma unroll
            for (int f = 0; f < 2; f++)
#pragma unroll
                for (int nf = 0; nf < 4; nf++) {
                    int p = nf >> 1, o = (nf & 1) * 2;
                    MMA16816(acc[f][nf], ah[f], bh[p][o], bh[p][o + 1]);
                }
#pragma unroll
            for (int f = 0; f < 2; f++)
#pragma unroll
                for (int nf = 0; nf < 4; nf++) {
                    int p = nf >> 1, o = (nf & 1) * 2;
                    MMA16816(acc[f][nf], ah[f], bl[p][o], bl[p][o + 1]);
                }
        }

        if (more) store_A(nxt, v, i + 1);
    }

    // ---- epilogue: out = relu(d * (acc + g)) ----
    int r0 = bm + wm * 32 + (lane >> 2);
    int c0 = bn + wn * 32 + (lane & 3) * 2;
#pragma unroll
    for (int f = 0; f < 2; f++) {
        int m1 = r0 + f * 16;
        int m2 = m1 + 8;
        float d1 = g_d[m1];
        float d2 = g_d[m2];
#pragma unroll
        for (int nf = 0; nf < 4; nf++) {
            int c = c0 + nf * 8;
            float2 g1 = *(const float2*)&g_g[(size_t)m1 * DOUT_ + c];
            float2 g2 = *(const float2*)&g_g[(size_t)m2 * DOUT_ + c];
            float2 o1, o2;
            o1.x = fmaxf(d1 * (acc[f][nf][0] + g1.x), 0.0f);
            o1.y = fmaxf(d1 * (acc[f][nf][1] + g1.y), 0.0f);
            o2.x = fmaxf(d2 * (acc[f][nf][2] + g2.x), 0.0f);
            o2.y = fmaxf(d2 * (acc[f][nf][3] + g2.y), 0.0f);
            *(float2*)&out[(size_t)m1 * DOUT_ + c] = o1;
            *(float2*)&out[(size_t)m2 * DOUT_ + c] = o2;
        }
    }
}

// ---------------------------------------------------------------------------
extern "C" void kernel_launch(void* const* d_in, const int* in_sizes, int n_in,
                              void* d_out, int out_size) {
    const float* x = (const float*)d_in[0];   // [8192, 256]
    const float* A = (const float*)d_in[1];   // [8192, 8192]
    const float* W = (const float*)d_in[2];   // [256, 256]
    float* out = (float*)d_out;

    const int N = N_GCN;
    const size_t out_elems = (size_t)N * DOUT_;

    int doCopy = ((size_t)out_size >= out_elems + (size_t)N * N) ? 1 : 0;
    float* Acopy = doCopy ? (out + out_elems) : (float*)0;

    cudaFuncSetAttribute(agemm_mma, cudaFuncAttributeMaxDynamicSharedMemorySize,
                         SMEM_TOTAL_C);

    // 1. degrees (read-only)
    deg_kernel<<<N, 256>>>(A, N);

    // 2. g = diag(d)*(x@W^T) fp32 + fp16 hi/lo transposed splits
    dim3 gridB(N / 64, DOUT_ / 64);
    xw_kernel<<<gridB, 256>>>(x, W);

    // 3. out = relu(diag(d)*(A@g + g)) via mma.sync, 16 warps, BK=64
    dim3 gridC(N / BM, DOUT_ / BN);
    agemm_mma<<<gridC, 512, SMEM_TOTAL_C>>>(A, out, Acopy, doCopy, N);
}

// round 13
// speedup vs baseline: 1.0568x; 1.0568x over previous
#include <cuda_runtime.h>
#include <cuda_fp16.h>
#include <cstdint>

#define EPS_F 1e-15f

static const int N_GCN  = 8192;
static const int DIN_   = 256;
static const int DOUT_  = 256;

// ---------------------------------------------------------------------------
// Scratch (__device__ globals; no cudaMalloc allowed)
// ---------------------------------------------------------------------------
__device__ float g_d[8192];
__device__ __align__(16) float  g_g[8192 * 256];            // g = d*(x@W^T) fp32, [m][n]
__device__ __align__(16) __half g_gT_h[256 * 8192];         // gT hi fp16, [n][k]
__device__ __align__(16) __half g_gT_l[256 * 8192];         // gT lo fp16, [n][k]

// ---------------------------------------------------------------------------
// PTX helpers (plain sm_103-legal: ldmatrix / mma.sync / cp.async)
// ---------------------------------------------------------------------------
__device__ __forceinline__ uint32_t smem_to_u32(const void* p) {
    uint32_t a;
    asm("{ .reg .u64 t; cvta.to.shared.u64 t, %1; cvt.u32.u64 %0, t; }" : "=r"(a) : "l"(p));
    return a;
}

#define LDMX4(R, addr) \
    asm volatile("ldmatrix.sync.aligned.m8n8.x4.shared.b16 {%0,%1,%2,%3}, [%4];" \
        : "=r"((R)[0]), "=r"((R)[1]), "=r"((R)[2]), "=r"((R)[3]) : "r"(addr))

#define MMA16816(d, a, b0, b1) \
    asm volatile("mma.sync.aligned.m16n8k16.row.col.f32.f16.f16.f32 " \
        "{%0,%1,%2,%3}, {%4,%5,%6,%7}, {%8,%9}, {%0,%1,%2,%3};" \
        : "+f"((d)[0]), "+f"((d)[1]), "+f"((d)[2]), "+f"((d)[3]) \
        : "r"((a)[0]), "r"((a)[1]), "r"((a)[2]), "r"((a)[3]), "r"(b0), "r"(b1))

// f16-accumulator variant: d,c are 2x b32 (packed half2). Used for the tiny
// lo-split term (values ~2^-12 of hi) -> rounding contribution ~1e-6 rel.
#define MMA16816F16(d, a, b0, b1) \
    asm volatile("mma.sync.aligned.m16n8k16.row.col.f16.f16.f16.f16 " \
        "{%0,%1}, {%2,%3,%4,%5}, {%6,%7}, {%0,%1};" \
        : "+r"((d)[0]), "+r"((d)[1]) \
        : "r"((a)[0]), "r"((a)[1]), "r"((a)[2]), "r"((a)[3]), "r"(b0), "r"(b1))

#define CP_ASYNC16(dst, src) \
    asm volatile("cp.async.cg.shared.global [%0], [%1], 16;" :: "r"(dst), "l"(src) : "memory")
#define CP_COMMIT() asm volatile("cp.async.commit_group;" ::: "memory")
#define CP_WAIT0()  asm volatile("cp.async.wait_group 0;" ::: "memory")

#define STG_CS_128(ptr, v) \
    asm volatile("st.global.cs.v4.f32 [%0], {%1,%2,%3,%4};" \
        :: "l"(ptr), "f"((v).x), "f"((v).y), "f"((v).z), "f"((v).w) : "memory")

__device__ __forceinline__ uint32_t h2u(__half2 v) { return *reinterpret_cast<uint32_t*>(&v); }

// ---------------------------------------------------------------------------
// Kernel A: read-only degree computation (proven: 80% HBM)
// ---------------------------------------------------------------------------
__global__ void deg_kernel(const float* __restrict__ A, int N) {
    int row = blockIdx.x;
    const float4* Ar = (const float4*)(A + (size_t)row * N);
    int n4 = N >> 2;
    float s = 0.0f;
    for (int j = threadIdx.x; j < n4; j += blockDim.x) {
        float4 v = Ar[j];
        s += (v.x > EPS_F ? 1.0f : 0.0f);
        s += (v.y > EPS_F ? 1.0f : 0.0f);
        s += (v.z > EPS_F ? 1.0f : 0.0f);
        s += (v.w > EPS_F ? 1.0f : 0.0f);
    }
    __shared__ float red[256];
    red[threadIdx.x] = s;
    __syncthreads();
    for (int off = 128; off > 0; off >>= 1) {
        if (threadIdx.x < off) red[threadIdx.x] += red[threadIdx.x + off];
        __syncthreads();
    }
    if (threadIdx.x == 0) g_d[row] = rsqrtf(1.0f + red[0]);
}

// ---------------------------------------------------------------------------
// Kernel B: g = d*(x@W^T) fp32 + transposed fp16 hi/lo splits (proven)
// ---------------------------------------------------------------------------
__global__ void xw_kernel(const float* __restrict__ x,
                          const float* __restrict__ W) {
    __shared__ float xs[16][68];
    __shared__ float ws[16][68];

    int bm = blockIdx.x * 64;
    int bn = blockIdx.y * 64;
    int tid = threadIdx.x;
    int tx = tid & 15;
    int ty = tid >> 4;

    float acc[4][4];
#pragma unroll
    for (int i = 0; i < 4; i++)
#pragma unroll
        for (int j = 0; j < 4; j++) acc[i][j] = 0.0f;

    for (int kt = 0; kt < DIN_; kt += 16) {
        {
            int r = tid >> 2, c = tid & 3;
            float4 v = *(const float4*)(x + (size_t)(bm + r) * DIN_ + kt + c * 4);
            xs[c * 4 + 0][r] = v.x; xs[c * 4 + 1][r] = v.y;
            xs[c * 4 + 2][r] = v.z; xs[c * 4 + 3][r] = v.w;
        }
        {
            int r = tid >> 2, c = tid & 3;
            float4 v = *(const float4*)(W + (size_t)(bn + r) * DIN_ + kt + c * 4);
            ws[c * 4 + 0][r] = v.x; ws[c * 4 + 1][r] = v.y;
            ws[c * 4 + 2][r] = v.z; ws[c * 4 + 3][r] = v.w;
        }
        __syncthreads();
#pragma unroll
        for (int k = 0; k < 16; k++) {
            float4 a = *(const float4*)&xs[k][ty * 4];
            float4 b = *(const float4*)&ws[k][tx * 4];
            float av[4] = {a.x, a.y, a.z, a.w};
            float bv[4] = {b.x, b.y, b.z, b.w};
#pragma unroll
            for (int i = 0; i < 4; i++)
#pragma unroll
                for (int j = 0; j < 4; j++) acc[i][j] += av[i] * bv[j];
        }
        __syncthreads();
    }

    int m0 = bm + ty * 4;
    float dm[4];
#pragma unroll
    for (int i = 0; i < 4; i++) dm[i] = g_d[m0 + i];

#pragma unroll
    for (int j = 0; j < 4; j++) {
        int n = bn + tx * 4 + j;
        float gv[4];
#pragma unroll
        for (int i = 0; i < 4; i++) {
            gv[i] = dm[i] * acc[i][j];
            g_g[(size_t)(m0 + i) * DOUT_ + n] = gv[i];
        }
        __half2 h01 = __floats2half2_rn(gv[0], gv[1]);
        __half2 h23 = __floats2half2_rn(gv[2], gv[3]);
        float2 f01 = __half22float2(h01);
        float2 f23 = __half22float2(h23);
        __half2 l01 = __floats2half2_rn(gv[0] - f01.x, gv[1] - f01.y);
        __half2 l23 = __floats2half2_rn(gv[2] - f23.x, gv[3] - f23.y);
        *(uint2*)(&g_gT_h[(size_t)n * N_GCN + m0]) = make_uint2(h2u(h01), h2u(h23));
        *(uint2*)(&g_gT_l[(size_t)n * N_GCN + m0]) = make_uint2(h2u(l01), h2u(l23));
    }
}

// ---------------------------------------------------------------------------
// Kernel C: warp-MMA GEMM (R10-proven config). out = relu(d*(A@g+g)) + A copy.
// CTA 128x128, BK=32, 16 warps (4M x 4N), warp tile 32x32.
// hi term (Ah*gh): f32 accumulate. lo term (Ah*gl): f16 accumulate (separate
// accumulator, summed in the epilogue) -- probes the f16-accum HMMA rate.
// Copy stores st.global.cs: keep 268MB passthrough out of L2.
// ---------------------------------------------------------------------------
static const int BM = 128, BN = 128, BK = 32;
static const int TSTRIDE = 80;
static const int TILE_B  = 128 * TSTRIDE;      // 10240 B
static const int BUF_B   = 3 * TILE_B;         // Ah, Bh, Bl = 30720 B
static const int SMEM_TOTAL_C = 2 * BUF_B;     // 61440 B (dynamic)

__global__ void __launch_bounds__(512, 1)
agemm_mma(const float* __restrict__ A, float* __restrict__ out,
          float* __restrict__ Acopy, int doCopy, int K) {
    extern __shared__ char smem[];
    uint32_t sbase = smem_to_u32(smem);

    int tid  = threadIdx.x;
    int lane = tid & 31;
    int wid  = tid >> 5;
    int wm = wid & 3;                  // 0..3 -> 32-row block
    int wn = wid >> 2;                 // 0..3 -> 32-col block
    int bm = blockIdx.x * BM;
    int by = blockIdx.y;
    int bn = by * BN;

    // A loader: each thread owns a quarter row (8 of 32 k) of the 128x32 tile
    int arow = tid >> 2;               // 0..127
    int aq   = tid & 3;                // 8 fp32 elems each
    const float* Aptr = A + (size_t)(bm + arow) * K + aq * 8;
    float* Cptr = Acopy ? (Acopy + (size_t)(bm + arow) * K + aq * 8) : (float*)0;
    uint32_t a_soff = (uint32_t)arow * TSTRIDE + aq * 16;

    uint32_t aoff0 = (uint32_t)(wm * 32 + (lane & 15)) * TSTRIDE + (lane >> 4) * 16;
    uint32_t brow  = (lane & 7) + ((lane >> 4) & 1) * 8;
    uint32_t boff0 = (uint32_t)(wn * 32 + brow) * TSTRIDE + ((lane >> 3) & 1) * 16;

    float acc[2][4][4];                // hi term, f32
    uint32_t accl[2][4][2];            // lo term, f16x2 pairs
#pragma unroll
    for (int f = 0; f < 2; f++)
#pragma unroll
        for (int n = 0; n < 4; n++) {
#pragma unroll
            for (int e = 0; e < 4; e++) acc[f][n][e] = 0.0f;
            accl[f][n][0] = 0u; accl[f][n][1] = 0u;
        }

    const int NC = K / BK;    // 256

    auto issue_B = [&](int buf, int kt) {
#pragma unroll
        for (int j = 0; j < 2; j++) {
            int id = j * 512 + tid;            // 0..1023
            int split = id >> 9;               // 0=hi, 1=lo
            int rem = id & 511;
            int n = rem >> 2, seg = rem & 3;
            const __half* src = (split ? g_gT_l : g_gT_h) + (size_t)(bn + n) * K + kt + seg * 8;
            uint32_t dst = sbase + buf * BUF_B + (1 + split) * TILE_B + n * TSTRIDE + seg * 16;
            CP_ASYNC16(dst, src);
        }
    };

    // store A hi tile (8 fp16 = one uint4) to smem; copy raw fp32 chunk (.cs)
    auto store_A = [&](int buf, const float4* v, int chunk) {
        __half2 ha = __floats2half2_rn(v[0].x, v[0].y);
        __half2 hb = __floats2half2_rn(v[0].z, v[0].w);
        __half2 hc = __floats2half2_rn(v[1].x, v[1].y);
        __half2 hd = __floats2half2_rn(v[1].z, v[1].w);
        *(uint4*)(smem + buf * BUF_B + a_soff) = make_uint4(h2u(ha), h2u(hb), h2u(hc), h2u(hd));
        if (doCopy && (chunk >> 7) == by) {
            float* cp = Cptr + (size_t)chunk * BK;
            STG_CS_128(cp + 0, v[0]);
            STG_CS_128(cp + 4, v[1]);
        }
    };

    // ---- prologue: chunk 0 -> buf 0 ----
    {
        float4 v[2];
        v[0] = *(const float4*)(Aptr + 0);
        v[1] = *(const float4*)(Aptr + 4);
        issue_B(0, 0);
        CP_COMMIT();
        store_A(0, v, 0);
    }

    for (int i = 0; i < NC; i++) {
        int cur = i & 1, nxt = cur ^ 1;
        CP_WAIT0();
        __syncthreads();

        float4 v[2];
        bool more = (i + 1) < NC;
        if (more) {
            const float* Ap = Aptr + (size_t)(i + 1) * BK;
            v[0] = *(const float4*)(Ap + 0);
            v[1] = *(const float4*)(Ap + 4);
            issue_B(nxt, (i + 1) * BK);
            CP_COMMIT();
        }

        uint32_t sa_h = sbase + cur * BUF_B;
        uint32_t sb_h = sa_h + TILE_B;
        uint32_t sb_l = sa_h + 2 * TILE_B;

#pragma unroll
        for (int kh = 0; kh < 2; kh++) {
            uint32_t ah[2][4], bh[2][4], bl[2][4];
            uint32_t ka = aoff0 + kh * 32;
            uint32_t kb = boff0 + kh * 32;
#pragma unroll
            for (int f = 0; f < 2; f++) LDMX4(ah[f], sa_h + ka + f * (16 * TSTRIDE));
#pragma unroll
            for (int p = 0; p < 2; p++) LDMX4(bh[p], sb_h + kb + p * (16 * TSTRIDE));
#pragma unroll
            for (int p = 0; p < 2; p++) LDMX4(bl[p], sb_l + kb + p * (16 * TSTRIDE));

            // hi term: f32 accumulate
#pragma unroll
            for (int f = 0; f < 2; f++)
#pragma unroll
                for (int nf = 0; nf < 4; nf++) {
                    int p = nf >> 1, o = (nf & 1) * 2;
                    MMA16816(acc[f][nf], ah[f], bh[p][o], bh[p][o + 1]);
                }
            // lo term: f16 accumulate (separate accumulator)
#pragma unroll
            for (int f = 0; f < 2; f++)
#pragma unroll
                for (int nf = 0; nf < 4; nf++) {
                    int p = nf >> 1, o = (nf & 1) * 2;
                    MMA16816F16(accl[f][nf], ah[f], bl[p][o], bl[p][o + 1]);
                }
        }

        if (more) store_A(nxt, v, i + 1);
    }

    // ---- epilogue: out = relu(d * (acc_hi + acc_lo + g)) ----
    int r0 = bm + wm * 32 + (lane >> 2);
    int c0 = bn + wn * 32 + (lane & 3) * 2;
#pragma unroll
    for (int f = 0; f < 2; f++) {
        int m1 = r0 + f * 16;
        int m2 = m1 + 8;
        float d1 = g_d[m1];
        float d2 = g_d[m2];
#pragma unroll
        for (int nf = 0; nf < 4; nf++) {
            int c = c0 + nf * 8;
            float2 g1 = *(const float2*)&g_g[(size_t)m1 * DOUT_ + c];
            float2 g2 = *(const float2*)&g_g[(size_t)m2 * DOUT_ + c];
            float2 lo1 = __half22float2(*reinterpret_cast<__half2*>(&accl[f][nf][0]));
            float2 lo2 = __half22float2(*reinterpret_cast<__half2*>(&accl[f][nf][1]));
            float2 o1, o2;
            o1.x = fmaxf(d1 * (acc[f][nf][0] + lo1.x + g1.x), 0.0f);
            o1.y = fmaxf(d1 * (acc[f][nf][1] + lo1.y + g1.y), 0.0f);
            o2.x = fmaxf(d2 * (acc[f][nf][2] + lo2.x + g2.x), 0.0f);
            o2.y = fmaxf(d2 * (acc[f][nf][3] + lo2.y + g2.y), 0.0f);
            *(float2*)&out[(size_t)m1 * DOUT_ + c] = o1;
            *(float2*)&out[(size_t)m2 * DOUT_ + c] = o2;
        }
    }
}

// ---------------------------------------------------------------------------
extern "C" void kernel_launch(void* const* d_in, const int* in_sizes, int n_in,
                              void* d_out, int out_size) {
    const float* x = (const float*)d_in[0];   // [8192, 256]
    const float* A = (const float*)d_in[1];   // [8192, 8192]
    const float* W = (const float*)d_in[2];   // [256, 256]
    float* out = (float*)d_out;

    const int N = N_GCN;
    const size_t out_elems = (size_t)N * DOUT_;

    int doCopy = ((size_t)out_size >= out_elems + (size_t)N * N) ? 1 : 0;
    float* Acopy = doCopy ? (out + out_elems) : (float*)0;

    cudaFuncSetAttribute(agemm_mma, cudaFuncAttributeMaxDynamicSharedMemorySize,
                         SMEM_TOTAL_C);

    // 1. degrees (read-only)
    deg_kernel<<<N, 256>>>(A, N);

    // 2. g = diag(d)*(x@W^T) fp32 + fp16 hi/lo transposed splits
    dim3 gridB(N / 64, DOUT_ / 64);
    xw_kernel<<<gridB, 256>>>(x, W);

    // 3. out = relu(diag(d)*(A@g + g)) via mma.sync, 16 warps, BK=32
    dim3 gridC(N / BM, DOUT_ / BN);
    agemm_mma<<<gridC, 512, SMEM_TOTAL_C>>>(A, out, Acopy, doCopy, N);
}

// round 14
// speedup vs baseline: 1.2327x; 1.1665x over previous
#include <cuda_runtime.h>
#include <cuda_fp16.h>
#include <cstdint>

#define EPS_F 1e-15f

static const int N_GCN  = 8192;
static const int DIN_   = 256;
static const int DOUT_  = 256;

// ---------------------------------------------------------------------------
// Scratch (__device__ globals; no cudaMalloc allowed)
// ---------------------------------------------------------------------------
__device__ float g_d[8192];
__device__ __align__(16) float  g_g[8192 * 256];            // g = d*(x@W^T) fp32, [m][n]
__device__ __align__(16) __half g_gT_h[256 * 8192];         // gT hi fp16, [n][k]

// ---------------------------------------------------------------------------
// PTX helpers (plain sm_103-legal: ldmatrix / mma.sync / cp.async)
// ---------------------------------------------------------------------------
__device__ __forceinline__ uint32_t smem_to_u32(const void* p) {
    uint32_t a;
    asm("{ .reg .u64 t; cvta.to.shared.u64 t, %1; cvt.u32.u64 %0, t; }" : "=r"(a) : "l"(p));
    return a;
}

#define LDMX4(R, addr) \
    asm volatile("ldmatrix.sync.aligned.m8n8.x4.shared.b16 {%0,%1,%2,%3}, [%4];" \
        : "=r"((R)[0]), "=r"((R)[1]), "=r"((R)[2]), "=r"((R)[3]) : "r"(addr))

#define MMA16816(d, a, b0, b1) \
    asm volatile("mma.sync.aligned.m16n8k16.row.col.f32.f16.f16.f32 " \
        "{%0,%1,%2,%3}, {%4,%5,%6,%7}, {%8,%9}, {%0,%1,%2,%3};" \
        : "+f"((d)[0]), "+f"((d)[1]), "+f"((d)[2]), "+f"((d)[3]) \
        : "r"((a)[0]), "r"((a)[1]), "r"((a)[2]), "r"((a)[3]), "r"(b0), "r"(b1))

#define CP_ASYNC16(dst, src) \
    asm volatile("cp.async.cg.shared.global [%0], [%1], 16;" :: "r"(dst), "l"(src) : "memory")
#define CP_COMMIT() asm volatile("cp.async.commit_group;" ::: "memory")
#define CP_WAIT0()  asm volatile("cp.async.wait_group 0;" ::: "memory")

__device__ __forceinline__ uint32_t h2u(__half2 v) { return *reinterpret_cast<uint32_t*>(&v); }

// ---------------------------------------------------------------------------
// Kernel A: read-only degree computation (proven: ~80% HBM)
// ---------------------------------------------------------------------------
__global__ void deg_kernel(const float* __restrict__ A, int N) {
    int row = blockIdx.x;
    const float4* Ar = (const float4*)(A + (size_t)row * N);
    int n4 = N >> 2;
    float s = 0.0f;
    for (int j = threadIdx.x; j < n4; j += blockDim.x) {
        float4 v = Ar[j];
        s += (v.x > EPS_F ? 1.0f : 0.0f);
        s += (v.y > EPS_F ? 1.0f : 0.0f);
        s += (v.z > EPS_F ? 1.0f : 0.0f);
        s += (v.w > EPS_F ? 1.0f : 0.0f);
    }
    __shared__ float red[256];
    red[threadIdx.x] = s;
    __syncthreads();
    for (int off = 128; off > 0; off >>= 1) {
        if (threadIdx.x < off) red[threadIdx.x] += red[threadIdx.x + off];
        __syncthreads();
    }
    if (threadIdx.x == 0) g_d[row] = rsqrtf(1.0f + red[0]);
}

// ---------------------------------------------------------------------------
// Kernel B: g = d*(x@W^T) fp32 + transposed fp16 hi split (lo no longer needed)
// ---------------------------------------------------------------------------
__global__ void xw_kernel(const float* __restrict__ x,
                          const float* __restrict__ W) {
    __shared__ float xs[16][68];
    __shared__ float ws[16][68];

    int bm = blockIdx.x * 64;
    int bn = blockIdx.y * 64;
    int tid = threadIdx.x;
    int tx = tid & 15;
    int ty = tid >> 4;

    float acc[4][4];
#pragma unroll
    for (int i = 0; i < 4; i++)
#pragma unroll
        for (int j = 0; j < 4; j++) acc[i][j] = 0.0f;

    for (int kt = 0; kt < DIN_; kt += 16) {
        {
            int r = tid >> 2, c = tid & 3;
            float4 v = *(const float4*)(x + (size_t)(bm + r) * DIN_ + kt + c * 4);
            xs[c * 4 + 0][r] = v.x; xs[c * 4 + 1][r] = v.y;
            xs[c * 4 + 2][r] = v.z; xs[c * 4 + 3][r] = v.w;
        }
        {
            int r = tid >> 2, c = tid & 3;
            float4 v = *(const float4*)(W + (size_t)(bn + r) * DIN_ + kt + c * 4);
            ws[c * 4 + 0][r] = v.x; ws[c * 4 + 1][r] = v.y;
            ws[c * 4 + 2][r] = v.z; ws[c * 4 + 3][r] = v.w;
        }
        __syncthreads();
#pragma unroll
        for (int k = 0; k < 16; k++) {
            float4 a = *(const float4*)&xs[k][ty * 4];
            float4 b = *(const float4*)&ws[k][tx * 4];
            float av[4] = {a.x, a.y, a.z, a.w};
            float bv[4] = {b.x, b.y, b.z, b.w};
#pragma unroll
            for (int i = 0; i < 4; i++)
#pragma unroll
                for (int j = 0; j < 4; j++) acc[i][j] += av[i] * bv[j];
        }
        __syncthreads();
    }

    int m0 = bm + ty * 4;
    float dm[4];
#pragma unroll
    for (int i = 0; i < 4; i++) dm[i] = g_d[m0 + i];

#pragma unroll
    for (int j = 0; j < 4; j++) {
        int n = bn + tx * 4 + j;
        float gv[4];
#pragma unroll
        for (int i = 0; i < 4; i++) {
            gv[i] = dm[i] * acc[i][j];
            g_g[(size_t)(m0 + i) * DOUT_ + n] = gv[i];
        }
        __half2 h01 = __floats2half2_rn(gv[0], gv[1]);
        __half2 h23 = __floats2half2_rn(gv[2], gv[3]);
        *(uint2*)(&g_gT_h[(size_t)n * N_GCN + m0]) = make_uint2(h2u(h01), h2u(h23));
    }
}

// ---------------------------------------------------------------------------
// Kernel C: warp-MMA GEMM (R10 skeleton, single-term fp16).
// out = relu(d * (Ah@gh + g)) + fused A passthrough copy.
// CTA 128x128, BK=32, 16 warps (4M x 4N), warp tile 32x32.
// Single fp16 term: quadrature error ~2.6e-4 (A-lo drop 1.8e-4 measured,
// g-lo drop ~1.8e-4 predicted by the same calibrated model).
// Dynamic SMEM 40KB double buffered (Ah, Bh); stride 80B, conflict-free LDSM.
// ---------------------------------------------------------------------------
static const int BM = 128, BN = 128, BK = 32;
static const int TSTRIDE = 80;
static const int TILE_B  = 128 * TSTRIDE;      // 10240 B
static const int BUF_B   = 2 * TILE_B;         // Ah, Bh = 20480 B
static const int SMEM_TOTAL_C = 2 * BUF_B;     // 40960 B (dynamic)

__global__ void __launch_bounds__(512, 1)
agemm_mma(const float* __restrict__ A, float* __restrict__ out,
          float* __restrict__ Acopy, int doCopy, int K) {
    extern __shared__ char smem[];
    uint32_t sbase = smem_to_u32(smem);

    int tid  = threadIdx.x;
    int lane = tid & 31;
    int wid  = tid >> 5;
    int wm = wid & 3;                  // 0..3 -> 32-row block
    int wn = wid >> 2;                 // 0..3 -> 32-col block
    int bm = blockIdx.x * BM;
    int by = blockIdx.y;
    int bn = by * BN;

    // A loader: each thread owns a quarter row (8 of 32 k) of the 128x32 tile
    int arow = tid >> 2;               // 0..127
    int aq   = tid & 3;                // 8 fp32 elems each
    const float* Aptr = A + (size_t)(bm + arow) * K + aq * 8;
    float* Cptr = Acopy ? (Acopy + (size_t)(bm + arow) * K + aq * 8) : (float*)0;
    uint32_t a_soff = (uint32_t)arow * TSTRIDE + aq * 16;

    uint32_t aoff0 = (uint32_t)(wm * 32 + (lane & 15)) * TSTRIDE + (lane >> 4) * 16;
    uint32_t brow  = (lane & 7) + ((lane >> 4) & 1) * 8;
    uint32_t boff0 = (uint32_t)(wn * 32 + brow) * TSTRIDE + ((lane >> 3) & 1) * 16;

    float acc[2][4][4];
#pragma unroll
    for (int f = 0; f < 2; f++)
#pragma unroll
        for (int n = 0; n < 4; n++)
#pragma unroll
            for (int e = 0; e < 4; e++) acc[f][n][e] = 0.0f;

    const int NC = K / BK;    // 256

    // B tile: 128 rows x 32 fp16 = 8KB = 512 x 16B segments; 1 per thread.
    auto issue_B = [&](int buf, int kt) {
        int n = tid >> 2, seg = tid & 3;
        const __half* src = g_gT_h + (size_t)(bn + n) * K + kt + seg * 8;
        uint32_t dst = sbase + buf * BUF_B + TILE_B + n * TSTRIDE + seg * 16;
        CP_ASYNC16(dst, src);
    };

    // store A hi tile (8 fp16 = one uint4) to smem; copy raw fp32 chunk
    auto store_A = [&](int buf, const float4* v, int chunk) {
        __half2 ha = __floats2half2_rn(v[0].x, v[0].y);
        __half2 hb = __floats2half2_rn(v[0].z, v[0].w);
        __half2 hc = __floats2half2_rn(v[1].x, v[1].y);
        __half2 hd = __floats2half2_rn(v[1].z, v[1].w);
        *(uint4*)(smem + buf * BUF_B + a_soff) = make_uint4(h2u(ha), h2u(hb), h2u(hc), h2u(hd));
        if (doCopy && (chunk >> 7) == by) {
            float* cp = Cptr + (size_t)chunk * BK;
            *(float4*)(cp + 0) = v[0];
            *(float4*)(cp + 4) = v[1];
        }
    };

    // ---- prologue: chunk 0 -> buf 0 ----
    {
        float4 v[2];
        v[0] = *(const float4*)(Aptr + 0);
        v[1] = *(const float4*)(Aptr + 4);
        issue_B(0, 0);
        CP_COMMIT();
        store_A(0, v, 0);
    }

    for (int i = 0; i < NC; i++) {
        int cur = i & 1, nxt = cur ^ 1;
        CP_WAIT0();
        __syncthreads();

        float4 v[2];
        bool more = (i + 1) < NC;
        if (more) {
            const float* Ap = Aptr + (size_t)(i + 1) * BK;
            v[0] = *(const float4*)(Ap + 0);
            v[1] = *(const float4*)(Ap + 4);
            issue_B(nxt, (i + 1) * BK);
            CP_COMMIT();
        }

        uint32_t sa_h = sbase + cur * BUF_B;
        uint32_t sb_h = sa_h + TILE_B;

#pragma unroll
        for (int kh = 0; kh < 2; kh++) {
            uint32_t ah[2][4], bh[2][4];
            uint32_t ka = aoff0 + kh * 32;
            uint32_t kb = boff0 + kh * 32;
#pragma unroll
            for (int f = 0; f < 2; f++) LDMX4(ah[f], sa_h + ka + f * (16 * TSTRIDE));
#pragma unroll
            for (int p = 0; p < 2; p++) LDMX4(bh[p], sb_h + kb + p * (16 * TSTRIDE));

#pragma unroll
            for (int f = 0; f < 2; f++)
#pragma unroll
                for (int nf = 0; nf < 4; nf++) {
                    int p = nf >> 1, o = (nf & 1) * 2;
                    MMA16816(acc[f][nf], ah[f], bh[p][o], bh[p][o + 1]);
                }
        }

        if (more) store_A(nxt, v, i + 1);
    }

    // ---- epilogue: out = relu(d * (acc + g)) ----
    int r0 = bm + wm * 32 + (lane >> 2);
    int c0 = bn + wn * 32 + (lane & 3) * 2;
#pragma unroll
    for (int f = 0; f < 2; f++) {
        int m1 = r0 + f * 16;
        int m2 = m1 + 8;
        float d1 = g_d[m1];
        float d2 = g_d[m2];
#pragma unroll
        for (int nf = 0; nf < 4; nf++) {
            int c = c0 + nf * 8;
            float2 g1 = *(const float2*)&g_g[(size_t)m1 * DOUT_ + c];
            float2 g2 = *(const float2*)&g_g[(size_t)m2 * DOUT_ + c];
            float2 o1, o2;
            o1.x = fmaxf(d1 * (acc[f][nf][0] + g1.x), 0.0f);
            o1.y = fmaxf(d1 * (acc[f][nf][1] + g1.y), 0.0f);
            o2.x = fmaxf(d2 * (acc[f][nf][2] + g2.x), 0.0f);
            o2.y = fmaxf(d2 * (acc[f][nf][3] + g2.y), 0.0f);
            *(float2*)&out[(size_t)m1 * DOUT_ + c] = o1;
            *(float2*)&out[(size_t)m2 * DOUT_ + c] = o2;
        }
    }
}

// ---------------------------------------------------------------------------
extern "C" void kernel_launch(void* const* d_in, const int* in_sizes, int n_in,
                              void* d_out, int out_size) {
    const float* x = (const float*)d_in[0];   // [8192, 256]
    const float* A = (const float*)d_in[1];   // [8192, 8192]
    const float* W = (const float*)d_in[2];   // [256, 256]
    float* out = (float*)d_out;

    const int N = N_GCN;
    const size_t out_elems = (size_t)N * DOUT_;

    int doCopy = ((size_t)out_size >= out_elems + (size_t)N * N) ? 1 : 0;
    float* Acopy = doCopy ? (out + out_elems) : (float*)0;

    cudaFuncSetAttribute(agemm_mma, cudaFuncAttributeMaxDynamicSharedMemorySize,
                         SMEM_TOTAL_C);

    // 1. degrees (read-only)
    deg_kernel<<<N, 256>>>(A, N);

    // 2. g = diag(d)*(x@W^T) fp32 + fp16 hi transposed split
    dim3 gridB(N / 64, DOUT_ / 64);
    xw_kernel<<<gridB, 256>>>(x, W);

    // 3. out = relu(diag(d)*(A@g + g)) via single-term fp16 mma.sync
    dim3 gridC(N / BM, DOUT_ / BN);
    agemm_mma<<<gridC, 512, SMEM_TOTAL_C>>>(A, out, Acopy, doCopy, N);
}

// round 16
// speedup vs baseline: 1.2819x; 1.0399x over previous
#include <cuda_runtime.h>
#include <cuda_fp16.h>
#include <cstdint>

#define EPS_F 1e-15f

static const int N_GCN  = 8192;
static const int DIN_   = 256;
static const int DOUT_  = 256;

// ---------------------------------------------------------------------------
// Scratch (__device__ globals; no cudaMalloc allowed)
// ---------------------------------------------------------------------------
__device__ float g_d[8192];
__device__ __align__(16) float  g_g[8192 * 256];            // g = d*(x@W^T) fp32, [m][n]
__device__ __align__(16) __half g_gT_h[256 * 8192];         // gT hi fp16, [n][k]
__device__ __align__(16) __half g_Ah[(size_t)8192 * 8192];  // A as fp16, [m][k]

// ---------------------------------------------------------------------------
// PTX helpers (plain sm_103-legal: ldmatrix / mma.sync / cp.async)
// ---------------------------------------------------------------------------
__device__ __forceinline__ uint32_t smem_to_u32(const void* p) {
    uint32_t a;
    asm("{ .reg .u64 t; cvta.to.shared.u64 t, %1; cvt.u32.u64 %0, t; }" : "=r"(a) : "l"(p));
    return a;
}

#define LDMX4(R, addr) \
    asm volatile("ldmatrix.sync.aligned.m8n8.x4.shared.b16 {%0,%1,%2,%3}, [%4];" \
        : "=r"((R)[0]), "=r"((R)[1]), "=r"((R)[2]), "=r"((R)[3]) : "r"(addr))

#define MMA16816(d, a, b0, b1) \
    asm volatile("mma.sync.aligned.m16n8k16.row.col.f32.f16.f16.f32 " \
        "{%0,%1,%2,%3}, {%4,%5,%6,%7}, {%8,%9}, {%0,%1,%2,%3};" \
        : "+f"((d)[0]), "+f"((d)[1]), "+f"((d)[2]), "+f"((d)[3]) \
        : "r"((a)[0]), "r"((a)[1]), "r"((a)[2]), "r"((a)[3]), "r"(b0), "r"(b1))

#define CP_ASYNC16(dst, src) \
    asm volatile("cp.async.cg.shared.global [%0], [%1], 16;" :: "r"(dst), "l"(src) : "memory")
#define CP_COMMIT() asm volatile("cp.async.commit_group;" ::: "memory")
#define CP_WAIT1()  asm volatile("cp.async.wait_group 1;" ::: "memory")

__device__ __forceinline__ uint32_t h2u(__half2 v) { return *reinterpret_cast<uint32_t*>(&v); }

// ---------------------------------------------------------------------------
// Kernel A: degrees + write A as fp16 (Ah) for the async GEMM A-path.
// ---------------------------------------------------------------------------
__global__ void deg_kernel(const float* __restrict__ A, int N) {
    int row = blockIdx.x;
    const float4* Ar = (const float4*)(A + (size_t)row * N);
    __half* Ah = g_Ah + (size_t)row * N;
    int n4 = N >> 2;
    float s = 0.0f;
    for (int j = threadIdx.x; j < n4; j += blockDim.x) {
        float4 v = Ar[j];
        s += (v.x > EPS_F ? 1.0f : 0.0f);
        s += (v.y > EPS_F ? 1.0f : 0.0f);
        s += (v.z > EPS_F ? 1.0f : 0.0f);
        s += (v.w > EPS_F ? 1.0f : 0.0f);
        __half2 h0 = __floats2half2_rn(v.x, v.y);
        __half2 h1 = __floats2half2_rn(v.z, v.w);
        *(uint2*)(Ah + j * 4) = make_uint2(h2u(h0), h2u(h1));
    }
    __shared__ float red[256];
    red[threadIdx.x] = s;
    __syncthreads();
    for (int off = 128; off > 0; off >>= 1) {
        if (threadIdx.x < off) red[threadIdx.x] += red[threadIdx.x + off];
        __syncthreads();
    }
    if (threadIdx.x == 0) g_d[row] = rsqrtf(1.0f + red[0]);
}

// ---------------------------------------------------------------------------
// Kernel B: g = d*(x@W^T) fp32 + transposed fp16 hi split (proven)
// ---------------------------------------------------------------------------
__global__ void xw_kernel(const float* __restrict__ x,
                          const float* __restrict__ W) {
    __shared__ float xs[16][68];
    __shared__ float ws[16][68];

    int bm = blockIdx.x * 64;
    int bn = blockIdx.y * 64;
    int tid = threadIdx.x;
    int tx = tid & 15;
    int ty = tid >> 4;

    float acc[4][4];
#pragma unroll
    for (int i = 0; i < 4; i++)
#pragma unroll
        for (int j = 0; j < 4; j++) acc[i][j] = 0.0f;

    for (int kt = 0; kt < DIN_; kt += 16) {
        {
            int r = tid >> 2, c = tid & 3;
            float4 v = *(const float4*)(x + (size_t)(bm + r) * DIN_ + kt + c * 4);
            xs[c * 4 + 0][r] = v.x; xs[c * 4 + 1][r] = v.y;
            xs[c * 4 + 2][r] = v.z; xs[c * 4 + 3][r] = v.w;
        }
        {
            int r = tid >> 2, c = tid & 3;
            float4 v = *(const float4*)(W + (size_t)(bn + r) * DIN_ + kt + c * 4);
            ws[c * 4 + 0][r] = v.x; ws[c * 4 + 1][r] = v.y;
            ws[c * 4 + 2][r] = v.z; ws[c * 4 + 3][r] = v.w;
        }
        __syncthreads();
#pragma unroll
        for (int k = 0; k < 16; k++) {
            float4 a = *(const float4*)&xs[k][ty * 4];
            float4 b = *(const float4*)&ws[k][tx * 4];
            float av[4] = {a.x, a.y, a.z, a.w};
            float bv[4] = {b.x, b.y, b.z, b.w};
#pragma unroll
            for (int i = 0; i < 4; i++)
#pragma unroll
                for (int j = 0; j < 4; j++) acc[i][j] += av[i] * bv[j];
        }
        __syncthreads();
    }

    int m0 = bm + ty * 4;
    float dm[4];
#pragma unroll
    for (int i = 0; i < 4; i++) dm[i] = g_d[m0 + i];

#pragma unroll
    for (int j = 0; j < 4; j++) {
        int n = bn + tx * 4 + j;
        float gv[4];
#pragma unroll
        for (int i = 0; i < 4; i++) {
            gv[i] = dm[i] * acc[i][j];
            g_g[(size_t)(m0 + i) * DOUT_ + n] = gv[i];
        }
        __half2 h01 = __floats2half2_rn(gv[0], gv[1]);
        __half2 h23 = __floats2half2_rn(gv[2], gv[3]);
        *(uint2*)(&g_gT_h[(size_t)n * N_GCN + m0]) = make_uint2(h2u(h01), h2u(h23));
    }
}

// ---------------------------------------------------------------------------
// Kernel C: warp-MMA GEMM, fully-async loads. out = relu(d*(Ah@gh + g)) + copy.
// CTA 128x128, BK=32, 16 warps (4M x 4N), warp tile 32x32.
// A tile AND B tile via cp.async from fp16 scratch; 3-stage pipeline
// (wait_group<=1, ~2-chunk prefetch) -> DRAM latency off the critical path.
// fp32 passthrough copy: independent LDG (issued pre-MMA) -> STG (post-MMA).
// ---------------------------------------------------------------------------
static const int BM = 128, BN = 128, BK = 32;
static const int TSTRIDE = 80;
static const int TILE_B  = 128 * TSTRIDE;      // 10240 B
static const int BUF_B   = 2 * TILE_B;         // Ah, Bh = 20480 B per stage
static const int STAGES  = 3;
static const int SMEM_TOTAL_C = STAGES * BUF_B; // 61440 B (dynamic)

__global__ void __launch_bounds__(512, 1)
agemm_mma(const float* __restrict__ A, float* __restrict__ out,
          float* __restrict__ Acopy, int doCopy, int K) {
    extern __shared__ char smem[];
    uint32_t sbase = smem_to_u32(smem);

    int tid  = threadIdx.x;
    int lane = tid & 31;
    int wid  = tid >> 5;
    int wm = wid & 3;                  // 0..3 -> 32-row block
    int wn = wid >> 2;                 // 0..3 -> 32-col block
    int bm = blockIdx.x * BM;
    int by = blockIdx.y;
    int bn = by * BN;

    // async A loader: tile 128 rows x 32 fp16 = 512 x 16B segs; 1/thread
    int ar = tid >> 2, aseg = tid & 3;
    const __half* Ahp = g_Ah + (size_t)(bm + ar) * K + aseg * 8;
    uint32_t a_dst0 = (uint32_t)ar * TSTRIDE + aseg * 16;

    // copy stream (fp32): each thread owns 8 floats of one row
    int crow = tid >> 2;
    int cq   = tid & 3;
    const float* Aptr = A + (size_t)(bm + crow) * K + cq * 8;
    float* Cptr = Acopy ? (Acopy + (size_t)(bm + crow) * K + cq * 8) : (float*)0;

    uint32_t aoff0 = (uint32_t)(wm * 32 + (lane & 15)) * TSTRIDE + (lane >> 4) * 16;
    uint32_t brow  = (lane & 7) + ((lane >> 4) & 1) * 8;
    uint32_t boff0 = (uint32_t)(wn * 32 + brow) * TSTRIDE + ((lane >> 3) & 1) * 16;

    float acc[2][4][4];
#pragma unroll
    for (int f = 0; f < 2; f++)
#pragma unroll
        for (int n = 0; n < 4; n++)
#pragma unroll
            for (int e = 0; e < 4; e++) acc[f][n][e] = 0.0f;

    const int NC = K / BK;    // 256

    auto issue_chunk = [&](int stage, int kt) {
        uint32_t base = sbase + stage * BUF_B;
        CP_ASYNC16(base + a_dst0, Ahp + kt);
        int n = tid >> 2, seg = tid & 3;
        const __half* src = g_gT_h + (size_t)(bn + n) * K + kt + seg * 8;
        CP_ASYNC16(base + TILE_B + n * TSTRIDE + seg * 16, src);
    };

    // ---- prologue: chunks 0,1 -> stages 0,1 ----
    issue_chunk(0, 0);
    CP_COMMIT();
    issue_chunk(1, BK);
    CP_COMMIT();

    for (int i = 0; i < NC; i++) {
        CP_WAIT1();            // chunk i complete (<=1 group pending)
        __syncthreads();       // all warps past chunk i-1 MMAs -> stage reuse safe

        // issue chunk i+2 into stage (i+2)%3 (empty commit keeps group count)
        if (i + 2 < NC) issue_chunk((i + 2) % STAGES, (i + 2) * BK);
        CP_COMMIT();

        // copy stream: LDG now (latency hides under MMAs), STG after
        float4 v0, v1;
        bool own = doCopy && ((i >> 7) == by);
        if (own) {
            const float* Ap = Aptr + (size_t)i * BK;
            v0 = *(const float4*)(Ap + 0);
            v1 = *(const float4*)(Ap + 4);
        }

        uint32_t sa = sbase + (i % STAGES) * BUF_B;
        uint32_t sb = sa + TILE_B;

#pragma unroll
        for (int kh = 0; kh < 2; kh++) {
            uint32_t ah[2][4], bh[2][4];
            uint32_t ka = aoff0 + kh * 32;
            uint32_t kb = boff0 + kh * 32;
#pragma unroll
            for (int f = 0; f < 2; f++) LDMX4(ah[f], sa + ka + f * (16 * TSTRIDE));
#pragma unroll
            for (int p = 0; p < 2; p++) LDMX4(bh[p], sb + kb + p * (16 * TSTRIDE));

#pragma unroll
            for (int f = 0; f < 2; f++)
#pragma unroll
                for (int nf = 0; nf < 4; nf++) {
                    int p = nf >> 1, o = (nf & 1) * 2;
                    MMA16816(acc[f][nf], ah[f], bh[p][o], bh[p][o + 1]);
                }
        }

        if (own) {
            float* cp = Cptr + (size_t)i * BK;
            *(float4*)(cp + 0) = v0;
            *(float4*)(cp + 4) = v1;
        }
    }

    // ---- epilogue: out = relu(d * (acc + g)) ----
    int r0 = bm + wm * 32 + (lane >> 2);
    int c0 = bn + wn * 32 + (lane & 3) * 2;
#pragma unroll
    for (int f = 0; f < 2; f++) {
        int m1 = r0 + f * 16;
        int m2 = m1 + 8;
        float d1 = g_d[m1];
        float d2 = g_d[m2];
#pragma unroll
        for (int nf = 0; nf < 4; nf++) {
            int c = c0 + nf * 8;
            float2 g1 = *(const float2*)&g_g[(size_t)m1 * DOUT_ + c];
            float2 g2 = *(const float2*)&g_g[(size_t)m2 * DOUT_ + c];
            float2 o1, o2;
            o1.x = fmaxf(d1 * (acc[f][nf][0] + g1.x), 0.0f);
            o1.y = fmaxf(d1 * (acc[f][nf][1] + g1.y), 0.0f);
            o2.x = fmaxf(d2 * (acc[f][nf][2] + g2.x), 0.0f);
            o2.y = fmaxf(d2 * (acc[f][nf][3] + g2.y), 0.0f);
            *(float2*)&out[(size_t)m1 * DOUT_ + c] = o1;
            *(float2*)&out[(size_t)m2 * DOUT_ + c] = o2;
        }
    }
}

// ---------------------------------------------------------------------------
extern "C" void kernel_launch(void* const* d_in, const int* in_sizes, int n_in,
                              void* d_out, int out_size) {
    const float* x = (const float*)d_in[0];   // [8192, 256]
    const float* A = (const float*)d_in[1];   // [8192, 8192]
    const float* W = (const float*)d_in[2];   // [256, 256]
    float* out = (float*)d_out;

    const int N = N_GCN;
    const size_t out_elems = (size_t)N * DOUT_;

    int doCopy = ((size_t)out_size >= out_elems + (size_t)N * N) ? 1 : 0;
    float* Acopy = doCopy ? (out + out_elems) : (float*)0;

    cudaFuncSetAttribute(agemm_mma, cudaFuncAttributeMaxDynamicSharedMemorySize,
                         SMEM_TOTAL_C);

    // 1. degrees + Ah fp16 conversion
    deg_kernel<<<N, 256>>>(A, N);

    // 2. g = diag(d)*(x@W^T) fp32 + fp16 hi transposed split
    dim3 gridB(N / 64, DOUT_ / 64);
    xw_kernel<<<gridB, 256>>>(x, W);

    // 3. out = relu(diag(d)*(A@g + g)); fully-async 3-stage fp16 GEMM + copy
    dim3 gridC(N / BM, DOUT_ / BN);
    agemm_mma<<<gridC, 512, SMEM_TOTAL_C>>>(A, out, Acopy, doCopy, N);
}